// round 16
// baseline (speedup 1.0000x reference)
#include <cuda_runtime.h>
#include <cuda_bf16.h>
#include <float.h>
#include <stdint.h>

#define NB 2048
#define NS 200
#define NSP 208
#define ND 64
#define NH 4
#define NH1 64
#define NH2 32
#define KST 213       // odd: Phase-E scalar column reads conflict-free
#define NTHR 512
#define RST 72        // padded row stride (elements) for bf16 B tiles

// ---- global prep buffers ----
__device__ float g_W1aT[16384];           // (Wk+Wd)^T  [n=h*64+j][k]
__device__ float g_W1bT[16384];           // Wkq^T      [n][k]
__device__ float g_W1c[16384];            // Wq-Wd      [h][k][j] (for c1 prep)
__device__ __nv_bfloat16 g_B2hi[128*RST]; // W2^T hi    [n=h*32+j][k] padded rows
__device__ __nv_bfloat16 g_B2lo[128*RST];
__device__ float g_C1[NB*256];            // c1 = q@(Wq-Wd)+b1

__global__ void prep_w1(const float* __restrict__ W1) {
    int e = blockIdx.x*256 + threadIdx.x;           // 0..16383
    if (e >= 16384) return;
    int k = e & 63;
    int n = e >> 6;
    int h = n >> 6, j = n & 63;
    const float* w = W1 + h*256*64;
    g_W1aT[e] = w[k*64+j] + w[(192+k)*64+j];
    g_W1bT[e] = w[(128+k)*64+j];
    g_W1c[h*4096 + k*64 + j] = w[(64+k)*64+j] - w[(192+k)*64+j];
}

__global__ void prep_w2(const float* __restrict__ W2) {
    int e = blockIdx.x*256 + threadIdx.x;           // over 128*RST = 9216
    if (e >= 128*RST) return;
    int k = e % RST;
    int n = e / RST;
    if (k >= 64) { g_B2hi[e] = __float2bfloat16(0.f); g_B2lo[e] = __float2bfloat16(0.f); return; }
    int h = n >> 5, j = n & 31;
    float v = W2[h*2048 + k*32 + j];
    __nv_bfloat16 hi = __float2bfloat16(v);
    g_B2hi[e] = hi;
    g_B2lo[e] = __float2bfloat16(v - __bfloat162float(hi));
}

__global__ void prep_c1(const float* __restrict__ query, const float* __restrict__ b1) {
    __shared__ float sq[32*64];
    int tid = threadIdx.x;
    int b0 = blockIdx.x * 32;
    for (int t = tid; t < 32*64; t += 256) sq[t] = query[b0*64 + t];
    __syncthreads();
    int h = tid >> 6, j = tid & 63;
    float bias = b1[h*64 + j];
    float acc[32];
    #pragma unroll
    for (int bb = 0; bb < 32; bb++) acc[bb] = bias;
    const float* wcol = g_W1c + h*4096 + j;
    #pragma unroll 4
    for (int i = 0; i < 64; i++) {
        float wv = wcol[i*64];
        #pragma unroll
        for (int bb = 0; bb < 32; bb++) acc[bb] = fmaf(sq[bb*64 + i], wv, acc[bb]);
    }
    for (int bb = 0; bb < 32; bb++) g_C1[(b0+bb)*256 + tid] = acc[bb];
}

// ---- helpers ----
__device__ __forceinline__ uint32_t pkbf(__nv_bfloat16 a, __nv_bfloat16 b) {
    __nv_bfloat162 t = __halves2bfloat162(a, b);
    return *reinterpret_cast<uint32_t*>(&t);
}
__device__ __forceinline__ void split2(float x, float y, uint32_t& hi, uint32_t& lo) {
    __nv_bfloat16 hx = __float2bfloat16(x), hy = __float2bfloat16(y);
    hi = pkbf(hx, hy);
    lo = pkbf(__float2bfloat16(x - __bfloat162float(hx)),
              __float2bfloat16(y - __bfloat162float(hy)));
}
__device__ __forceinline__ void mma16816(float* d, const uint32_t* a, const uint32_t* b) {
    asm volatile("mma.sync.aligned.m16n8k16.row.col.f32.bf16.bf16.f32 "
        "{%0,%1,%2,%3}, {%4,%5,%6,%7}, {%8,%9}, {%0,%1,%2,%3};"
        : "+f"(d[0]), "+f"(d[1]), "+f"(d[2]), "+f"(d[3])
        : "r"(a[0]), "r"(a[1]), "r"(a[2]), "r"(a[3]), "r"(b[0]), "r"(b[1]));
}
__device__ __forceinline__ void ldm4(uint32_t& r0, uint32_t& r1, uint32_t& r2, uint32_t& r3,
                                     uint32_t addr) {
    asm volatile("ldmatrix.sync.aligned.m8n8.x4.shared.b16 {%0,%1,%2,%3}, [%4];"
        : "=r"(r0), "=r"(r1), "=r"(r2), "=r"(r3) : "r"(addr));
}

// ---- smem layout (bytes) ----
#define SM_K     0          // fp32 keys [64][KST] = 54528 (loaded once, used in Phase E)
#define SM_B1HI  54528      // W1ab^T hi [n=256][RST] = 36864
#define SM_B1LO  91392
#define SM_B2HI  128256     // W2^T hi [n=128][RST] = 18432
#define SM_B2LO  146688
#define SM_SC    165120     // 4*208 f32
#define SM_C1    168448     // 256 f32
#define SM_MASK  169472     // 208 f32 (+pad)
#define SM_W3    170304     // 128 f32
#define SM_B2B   170816     // 128 f32
#define SM_MISC  171328     // b3[0..3] a1[4..7] a2[8..11] comb[16..79]
#define SM_Q     171712     // 64 f32
#define SM_OUTH  171968     // 256 f32
#define SMEM_BYTES 172992

__global__ __launch_bounds__(NTHR, 1)
void attn_main(const float* __restrict__ query,
               const float* __restrict__ keys,
               const int*   __restrict__ kmask,
               const float* __restrict__ a1,
               const float* __restrict__ b2,
               const float* __restrict__ a2,
               const float* __restrict__ W3,
               const float* __restrict__ b3,
               const float* __restrict__ Wo,
               const float* __restrict__ bo,
               float* __restrict__ out)
{
    extern __shared__ char smc[];
    float* sKf   = (float*)(smc + SM_K);
    float* sScf  = (float*)(smc + SM_SC);
    float* sC1f  = (float*)(smc + SM_C1);
    float* sMaskf= (float*)(smc + SM_MASK);
    float* sW3f  = (float*)(smc + SM_W3);
    float* sB2bf = (float*)(smc + SM_B2B);
    float* sMiscf= (float*)(smc + SM_MISC);
    float* sQf   = (float*)(smc + SM_Q);
    float* sOutH = (float*)(smc + SM_OUTH);
    const uint32_t smb = (uint32_t)__cvta_generic_to_shared(smc);

    const int b = blockIdx.x;
    const int tid = threadIdx.x;
    const int wid = tid >> 5, lane = tid & 31;
    const int gr = lane >> 2, gc = lane & 3;

    // ---- Phase A ----
    for (int t = tid; t < 256; t += NTHR) sC1f[t] = g_C1[b*256 + t];
    if (tid < NH*NH2) { sW3f[tid] = W3[tid]; sB2bf[tid] = b2[tid]; }
    if (tid < ND) sQf[tid] = query[b*ND + tid];
    if (tid < NH) { sMiscf[tid] = b3[tid]; sMiscf[4+tid] = a1[tid]; sMiscf[8+tid] = a2[tid]; }
    if (tid < NSP) {
        float v = 0.f;
        if (tid < NS) v = (kmask[b*NS + tid] != 0) ? 1.f : 0.f;
        sMaskf[tid] = v;
    }
    for (int t = tid; t < 1152; t += NTHR) {
        ((uint4*)(smc+SM_B2HI))[t] = ((const uint4*)g_B2hi)[t];
        ((uint4*)(smc+SM_B2LO))[t] = ((const uint4*)g_B2lo)[t];
    }
    // fp32 keys -> sKf[d][s] once (Phase E); pad cols 200..212
    {
        for (int t = tid; t < 832; t += NTHR) {
            int d = t / 13, p = 200 + t % 13;
            sKf[d*KST + p] = 0.f;
        }
        const float4* kg = (const float4*)(keys + (size_t)b * (NS*ND));
        for (int t = tid; t < 3200; t += NTHR) {
            float4 v = kg[t];
            int e = t*4, s = e>>6, d = e&63;
            float* dst = sKf + d*KST + s;
            dst[0*KST]=v.x; dst[1*KST]=v.y; dst[2*KST]=v.z; dst[3*KST]=v.w;
        }
    }
    __syncthreads();   // sQf ready for fold

    // B1 fold: 2 adjacent k per thread, uint32 stores
    for (int t = tid; t < 8192; t += NTHR) {
        int k = (t & 31) * 2, n = t >> 5;
        int e = n*64 + k;
        float va = fmaf(sQf[k],   g_W1bT[e],   g_W1aT[e]);
        float vb = fmaf(sQf[k+1], g_W1bT[e+1], g_W1aT[e+1]);
        uint32_t hi, lo;
        split2(va, vb, hi, lo);
        uint32_t off = (uint32_t)(n*RST + k) * 2u;
        *(uint32_t*)(smc + SM_B1HI + off) = hi;
        *(uint32_t*)(smc + SM_B1LO + off) = lo;
    }

    // ---- A fragments straight from global keys (bit-identical to old staged path) ----
    uint32_t ahi[4][4], alo[4][4];
    {
        const float* kb = keys + (size_t)b * (NS*ND);
        const int row0 = wid*16 + gr;
        const int row1 = row0 + 8;
        const bool v0 = row0 < NS, v1 = row1 < NS;
        const float2 z2 = make_float2(0.f, 0.f);
        #pragma unroll
        for (int kc = 0; kc < 4; kc++) {
            int k0 = kc*16 + 2*gc;
            float2 f00 = v0 ? *(const float2*)(kb + row0*ND + k0)     : z2;
            float2 f10 = v1 ? *(const float2*)(kb + row1*ND + k0)     : z2;
            float2 f01 = v0 ? *(const float2*)(kb + row0*ND + k0 + 8) : z2;
            float2 f11 = v1 ? *(const float2*)(kb + row1*ND + k0 + 8) : z2;
            split2(f00.x, f00.y, ahi[kc][0], alo[kc][0]);
            split2(f10.x, f10.y, ahi[kc][1], alo[kc][1]);
            split2(f01.x, f01.y, ahi[kc][2], alo[kc][2]);
            split2(f11.x, f11.y, ahi[kc][3], alo[kc][3]);
        }
    }
    __syncthreads();   // B1 tiles ready

    // ---- ldmatrix lane offset for B tiles ----
    const int lm = lane >> 3;            // matrix index 0..3
    const int lr = lane & 7;             // row within matrix
    const uint32_t bOff = (uint32_t)((((lm>>1)*8 + lr)*RST + (lm&1)*8) * 2);

    // ---- Phase C: per-head GEMM1 -> epilogue -> GEMM2 -> scores ----
    #pragma unroll 1
    for (int h = 0; h < NH; h++) {
        const float al1 = sMiscf[4+h];
        const float al2 = sMiscf[8+h];

        float acc[8][4];
        #pragma unroll
        for (int nf = 0; nf < 8; nf++)
            #pragma unroll
            for (int r = 0; r < 4; r++) acc[nf][r] = 0.f;

        // B1hi loop: feeds BOTH (ahi x bhi) and (alo x bhi)
        {
            const uint32_t bbase = smb + SM_B1HI + (uint32_t)(h*64*RST*2) + bOff;
            #pragma unroll
            for (int kc = 0; kc < 4; kc++) {
                uint32_t bf[8][2];
                #pragma unroll
                for (int q = 0; q < 4; q++)
                    ldm4(bf[2*q][0], bf[2*q][1], bf[2*q+1][0], bf[2*q+1][1],
                         bbase + (uint32_t)(q*16*RST*2) + kc*32);
                #pragma unroll
                for (int nf = 0; nf < 8; nf++)
                    mma16816(acc[nf], ahi[kc], bf[nf]);
                #pragma unroll
                for (int nf = 0; nf < 8; nf++)
                    mma16816(acc[nf], alo[kc], bf[nf]);
            }
        }
        // B1lo loop: feeds (ahi x blo) only
        {
            const uint32_t bbase = smb + SM_B1LO + (uint32_t)(h*64*RST*2) + bOff;
            #pragma unroll
            for (int kc = 0; kc < 4; kc++) {
                uint32_t bf[8][2];
                #pragma unroll
                for (int q = 0; q < 4; q++)
                    ldm4(bf[2*q][0], bf[2*q][1], bf[2*q+1][0], bf[2*q+1][1],
                         bbase + (uint32_t)(q*16*RST*2) + kc*32);
                #pragma unroll
                for (int nf = 0; nf < 8; nf++)
                    mma16816(acc[nf], ahi[kc], bf[nf]);
            }
        }

        // epilogue 1: +c1, PReLU -> split into A2 fragments (C->A remap)
        uint32_t a2h[4][4], a2l[4][4];
        #pragma unroll
        for (int nf = 0; nf < 8; nf++) {
            float2 c1v = *(const float2*)(sC1f + h*64 + nf*8 + 2*gc);
            float v0 = acc[nf][0] + c1v.x;
            float v1 = acc[nf][1] + c1v.y;
            float v2 = acc[nf][2] + c1v.x;
            float v3 = acc[nf][3] + c1v.y;
            acc[nf][0] = v0 > 0.f ? v0 : al1*v0;
            acc[nf][1] = v1 > 0.f ? v1 : al1*v1;
            acc[nf][2] = v2 > 0.f ? v2 : al1*v2;
            acc[nf][3] = v3 > 0.f ? v3 : al1*v3;
        }
        #pragma unroll
        for (int kc = 0; kc < 4; kc++) {
            const float* cA = acc[2*kc];
            const float* cB = acc[2*kc+1];
            split2(cA[0], cA[1], a2h[kc][0], a2l[kc][0]);
            split2(cA[2], cA[3], a2h[kc][1], a2l[kc][1]);
            split2(cB[0], cB[1], a2h[kc][2], a2l[kc][2]);
            split2(cB[2], cB[3], a2h[kc][3], a2l[kc][3]);
        }

        // GEMM2: acc2[4n]
        float acc2[4][4];
        #pragma unroll
        for (int nf = 0; nf < 4; nf++)
            #pragma unroll
            for (int r = 0; r < 4; r++) acc2[nf][r] = 0.f;

        // B2hi loop: feeds (a2h x bhi) and (a2l x bhi)
        {
            const uint32_t bbase = smb + SM_B2HI + (uint32_t)(h*32*RST*2) + bOff;
            #pragma unroll
            for (int kc = 0; kc < 4; kc++) {
                uint32_t bf[4][2];
                #pragma unroll
                for (int q = 0; q < 2; q++)
                    ldm4(bf[2*q][0], bf[2*q][1], bf[2*q+1][0], bf[2*q+1][1],
                         bbase + (uint32_t)(q*16*RST*2) + kc*32);
                #pragma unroll
                for (int nf = 0; nf < 4; nf++)
                    mma16816(acc2[nf], a2h[kc], bf[nf]);
                #pragma unroll
                for (int nf = 0; nf < 4; nf++)
                    mma16816(acc2[nf], a2l[kc], bf[nf]);
            }
        }
        // B2lo loop: feeds (a2h x blo)
        {
            const uint32_t bbase = smb + SM_B2LO + (uint32_t)(h*32*RST*2) + bOff;
            #pragma unroll
            for (int kc = 0; kc < 4; kc++) {
                uint32_t bf[4][2];
                #pragma unroll
                for (int q = 0; q < 2; q++)
                    ldm4(bf[2*q][0], bf[2*q][1], bf[2*q+1][0], bf[2*q+1][1],
                         bbase + (uint32_t)(q*16*RST*2) + kc*32);
                #pragma unroll
                for (int nf = 0; nf < 4; nf++)
                    mma16816(acc2[nf], a2h[kc], bf[nf]);
            }
        }

        // epilogue 2: +b2, PReLU, dot W3, 4-lane reduce -> scores
        const float b3h = sMiscf[h];
        {
            float p0 = 0.f, p1 = 0.f;
            #pragma unroll
            for (int nf = 0; nf < 4; nf++) {
                int j0 = h*32 + nf*8 + 2*gc;
                float2 bb = *(const float2*)(sB2bf + j0);
                float2 ww = *(const float2*)(sW3f + j0);
                float v0 = acc2[nf][0] + bb.x;
                float v1 = acc2[nf][1] + bb.y;
                float v2 = acc2[nf][2] + bb.x;
                float v3 = acc2[nf][3] + bb.y;
                v0 = v0 > 0.f ? v0 : al2*v0;
                v1 = v1 > 0.f ? v1 : al2*v1;
                v2 = v2 > 0.f ? v2 : al2*v2;
                v3 = v3 > 0.f ? v3 : al2*v3;
                p0 = fmaf(v0, ww.x, fmaf(v1, ww.y, p0));
                p1 = fmaf(v2, ww.x, fmaf(v3, ww.y, p1));
            }
            p0 += __shfl_xor_sync(0xffffffffu, p0, 1);
            p0 += __shfl_xor_sync(0xffffffffu, p0, 2);
            p1 += __shfl_xor_sync(0xffffffffu, p1, 1);
            p1 += __shfl_xor_sync(0xffffffffu, p1, 2);
            if (gc == 0) {
                int s = wid*16 + gr;
                if (s < NSP)   sScf[h*NSP + s]   = (sMaskf[s]   != 0.f) ? (p0 + b3h) : -FLT_MAX;
                if (s+8 < NSP) sScf[h*NSP + s+8] = (sMaskf[s+8] != 0.f) ? (p1 + b3h) : -FLT_MAX;
            }
        }
    }
    __syncthreads();

    // ---- Phase D: masked softmax per head (warps 0-3) ----
    if (wid < NH) {
        float* row = sScf + wid*NSP;
        float m = -FLT_MAX;
        for (int t = lane; t < NS; t += 32) m = fmaxf(m, row[t]);
        #pragma unroll
        for (int o = 16; o > 0; o >>= 1) m = fmaxf(m, __shfl_xor_sync(0xffffffffu, m, o));
        float sum = 0.f;
        for (int t = lane; t < NS; t += 32) {
            float v = row[t];
            float e = (v > -1e38f) ? expf(v - m) : 0.f;
            row[t] = e;
            sum += e;
        }
        #pragma unroll
        for (int o = 16; o > 0; o >>= 1) sum += __shfl_xor_sync(0xffffffffu, sum, o);
        float inv = (sum > 0.f) ? (1.f / sum) : 0.f;
        for (int t = lane; t < NS; t += 32) row[t] *= inv;
    }
    __syncthreads();

    // ---- Phase E: weighted sum, head mean, out projection ----
    if (tid < NH*ND) {
        int h = tid >> 6, d = tid & 63;
        const float* w    = sScf + h*NSP;
        const float* kcol = sKf + d*KST;
        float a0 = 0.f, a1_ = 0.f, a2_ = 0.f, a3_ = 0.f;
        #pragma unroll 4
        for (int t = 0; t < NS; t += 4) {
            a0  = fmaf(w[t  ], kcol[t  ], a0);
            a1_ = fmaf(w[t+1], kcol[t+1], a1_);
            a2_ = fmaf(w[t+2], kcol[t+2], a2_);
            a3_ = fmaf(w[t+3], kcol[t+3], a3_);
        }
        sOutH[tid] = (a0 + a1_) + (a2_ + a3_);
    }
    __syncthreads();
    if (tid < ND) {
        float c = 0.25f * (sOutH[tid] + sOutH[64+tid] + sOutH[128+tid] + sOutH[192+tid]);
        sMiscf[16 + tid] = c;
    }
    __syncthreads();
    if (tid < ND) {
        float e0 = bo[tid], e1 = 0.f;
        #pragma unroll 4
        for (int d2 = 0; d2 < ND; d2 += 2) {
            e0 = fmaf(sMiscf[16 + d2],     Wo[(d2  )*ND + tid], e0);
            e1 = fmaf(sMiscf[16 + d2 + 1], Wo[(d2+1)*ND + tid], e1);
        }
        out[b*ND + tid] = e0 + e1;
    }
}

extern "C" void kernel_launch(void* const* d_in, const int* in_sizes, int n_in,
                              void* d_out, int out_size) {
    const float* query = (const float*)d_in[0];
    const float* keys  = (const float*)d_in[1];
    const int*   kmask = (const int*)  d_in[2];
    const float* W1    = (const float*)d_in[3];
    const float* b1    = (const float*)d_in[4];
    const float* a1    = (const float*)d_in[5];
    const float* W2    = (const float*)d_in[6];
    const float* b2    = (const float*)d_in[7];
    const float* a2    = (const float*)d_in[8];
    const float* W3    = (const float*)d_in[9];
    const float* b3    = (const float*)d_in[10];
    const float* Wo    = (const float*)d_in[11];
    const float* bo    = (const float*)d_in[12];
    float* out = (float*)d_out;

    cudaFuncSetAttribute(attn_main, cudaFuncAttributeMaxDynamicSharedMemorySize, SMEM_BYTES);

    prep_w1<<<64, 256>>>(W1);
    prep_w2<<<36, 256>>>(W2);
    prep_c1<<<64, 256>>>(query, b1);
    attn_main<<<NB, NTHR, SMEM_BYTES>>>(
        query, keys, kmask, a1, b2, a2, W3, b3, Wo, bo, out);
}

// round 17
// speedup vs baseline: 1.0033x; 1.0033x over previous
#include <cuda_runtime.h>
#include <cuda_bf16.h>
#include <float.h>
#include <stdint.h>

#define NB 2048
#define NS 200
#define NSP 208
#define ND 64
#define NH 4
#define NH1 64
#define NH2 32
#define KST 213       // odd: Phase-E scalar column reads conflict-free
#define NTHR 512
#define RST 72        // padded row stride (elements) for all bf16 MMA tiles

// ---- global prep buffers ----
__device__ float g_W1aT[16384];           // (Wk+Wd)^T  [n=h*64+j][k]
__device__ float g_W1bT[16384];           // Wkq^T      [n][k]
__device__ float g_W1c[16384];            // Wq-Wd      [h][k][j] (for c1 prep)
__device__ __nv_bfloat16 g_B2hi[128*RST]; // W2^T hi    [n=h*32+j][k] padded rows
__device__ __nv_bfloat16 g_B2lo[128*RST];
__device__ float g_C1[NB*256];            // c1 = q@(Wq-Wd)+b1

__global__ void prep_w1(const float* __restrict__ W1) {
    int e = blockIdx.x*256 + threadIdx.x;           // 0..16383
    if (e >= 16384) return;
    int k = e & 63;
    int n = e >> 6;
    int h = n >> 6, j = n & 63;
    const float* w = W1 + h*256*64;
    g_W1aT[e] = w[k*64+j] + w[(192+k)*64+j];
    g_W1bT[e] = w[(128+k)*64+j];
    g_W1c[h*4096 + k*64 + j] = w[(64+k)*64+j] - w[(192+k)*64+j];
}

__global__ void prep_w2(const float* __restrict__ W2) {
    int e = blockIdx.x*256 + threadIdx.x;           // over 128*RST = 9216
    if (e >= 128*RST) return;
    int k = e % RST;
    int n = e / RST;
    if (k >= 64) { g_B2hi[e] = __float2bfloat16(0.f); g_B2lo[e] = __float2bfloat16(0.f); return; }
    int h = n >> 5, j = n & 31;
    float v = W2[h*2048 + k*32 + j];
    __nv_bfloat16 hi = __float2bfloat16(v);
    g_B2hi[e] = hi;
    g_B2lo[e] = __float2bfloat16(v - __bfloat162float(hi));
}

__global__ void prep_c1(const float* __restrict__ query, const float* __restrict__ b1) {
    __shared__ float sq[32*64];
    int tid = threadIdx.x;
    int b0 = blockIdx.x * 32;
    for (int t = tid; t < 32*64; t += 256) sq[t] = query[b0*64 + t];
    __syncthreads();
    int h = tid >> 6, j = tid & 63;
    float bias = b1[h*64 + j];
    float acc[32];
    #pragma unroll
    for (int bb = 0; bb < 32; bb++) acc[bb] = bias;
    const float* wcol = g_W1c + h*4096 + j;
    #pragma unroll 4
    for (int i = 0; i < 64; i++) {
        float wv = wcol[i*64];
        #pragma unroll
        for (int bb = 0; bb < 32; bb++) acc[bb] = fmaf(sq[bb*64 + i], wv, acc[bb]);
    }
    for (int bb = 0; bb < 32; bb++) g_C1[(b0+bb)*256 + tid] = acc[bb];
}

// ---- helpers ----
__device__ __forceinline__ uint32_t pkbf(__nv_bfloat16 a, __nv_bfloat16 b) {
    __nv_bfloat162 t = __halves2bfloat162(a, b);
    return *reinterpret_cast<uint32_t*>(&t);
}
__device__ __forceinline__ void split2(float x, float y, uint32_t& hi, uint32_t& lo) {
    __nv_bfloat16 hx = __float2bfloat16(x), hy = __float2bfloat16(y);
    hi = pkbf(hx, hy);
    lo = pkbf(__float2bfloat16(x - __bfloat162float(hx)),
              __float2bfloat16(y - __bfloat162float(hy)));
}
__device__ __forceinline__ void mma16816(float* d, const uint32_t* a, const uint32_t* b) {
    asm volatile("mma.sync.aligned.m16n8k16.row.col.f32.bf16.bf16.f32 "
        "{%0,%1,%2,%3}, {%4,%5,%6,%7}, {%8,%9}, {%0,%1,%2,%3};"
        : "+f"(d[0]), "+f"(d[1]), "+f"(d[2]), "+f"(d[3])
        : "r"(a[0]), "r"(a[1]), "r"(a[2]), "r"(a[3]), "r"(b[0]), "r"(b[1]));
}
__device__ __forceinline__ void ldm4(uint32_t& r0, uint32_t& r1, uint32_t& r2, uint32_t& r3,
                                     uint32_t addr) {
    asm volatile("ldmatrix.sync.aligned.m8n8.x4.shared.b16 {%0,%1,%2,%3}, [%4];"
        : "=r"(r0), "=r"(r1), "=r"(r2), "=r"(r3) : "r"(addr));
}

// ---- smem layout (bytes) ----
#define SM_AHI   0          // keys hi [s=256][RST] bf16 = 36864
#define SM_ALO   36864
#define SM_B1HI  73728      // W1ab^T hi [n=256][RST]
#define SM_B1LO  110592
#define SM_B2HI  147456     // W2^T hi [n=128][RST] = 18432
#define SM_B2LO  165888
#define SM_SC    184320     // 4*208 f32
#define SM_C1    187648     // 256 f32
#define SM_MASK  188672     // 208 f32 (+pad)
#define SM_W3    189504     // 128 f32
#define SM_B2B   190016     // 128 f32
#define SM_MISC  190528     // b3[0..3] a1[4..7] a2[8..11] comb[16..79]
#define SM_Q     190912     // 64 f32
#define SM_OUTH  191168     // 256 f32
#define SMEM_BYTES 192192
// Phase E reuses [0 .. 54528) (dead A-tile region) for fp32 keys [64][KST]

__global__ __launch_bounds__(NTHR, 1)
void attn_main(const float* __restrict__ query,
               const float* __restrict__ keys,
               const int*   __restrict__ kmask,
               const float* __restrict__ a1,
               const float* __restrict__ b2,
               const float* __restrict__ a2,
               const float* __restrict__ W3,
               const float* __restrict__ b3,
               const float* __restrict__ Wo,
               const float* __restrict__ bo,
               float* __restrict__ out)
{
    extern __shared__ char smc[];
    float* sScf  = (float*)(smc + SM_SC);
    float* sC1f  = (float*)(smc + SM_C1);
    float* sMaskf= (float*)(smc + SM_MASK);
    float* sW3f  = (float*)(smc + SM_W3);
    float* sB2bf = (float*)(smc + SM_B2B);
    float* sMiscf= (float*)(smc + SM_MISC);
    float* sQf   = (float*)(smc + SM_Q);
    float* sOutH = (float*)(smc + SM_OUTH);
    float* sKf   = (float*)(smc);          // Phase E only
    const uint32_t smb = (uint32_t)__cvta_generic_to_shared(smc);

    const int b = blockIdx.x;
    const int tid = threadIdx.x;
    const int wid = tid >> 5, lane = tid & 31;
    const int gc = lane & 3;

    // ---- Phase A ----
    for (int t = tid; t < 256; t += NTHR) sC1f[t] = g_C1[b*256 + t];
    if (tid < NH*NH2) { sW3f[tid] = W3[tid]; sB2bf[tid] = b2[tid]; }
    if (tid < ND) sQf[tid] = query[b*ND + tid];
    if (tid < NH) { sMiscf[tid] = b3[tid]; sMiscf[4+tid] = a1[tid]; sMiscf[8+tid] = a2[tid]; }
    if (tid < NSP) {
        float v = 0.f;
        if (tid < NS) v = (kmask[b*NS + tid] != 0) ? 1.f : 0.f;
        sMaskf[tid] = v;
    }
    for (int t = tid; t < 1152; t += NTHR) {
        ((uint4*)(smc+SM_B2HI))[t] = ((const uint4*)g_B2hi)[t];
        ((uint4*)(smc+SM_B2LO))[t] = ((const uint4*)g_B2lo)[t];
    }
    for (int t = tid; t < 504; t += NTHR) {
        ((uint4*)(smc + SM_AHI + 200*144))[t] = make_uint4(0,0,0,0);
        ((uint4*)(smc + SM_ALO + 200*144))[t] = make_uint4(0,0,0,0);
    }
    {
        const float4* kg = (const float4*)(keys + (size_t)b * (NS*ND));
        for (int t = tid; t < 3200; t += NTHR) {
            float4 v = kg[t];
            int e = t*4, s = e>>6, k = e&63;
            uint32_t h01, l01, h23, l23;
            split2(v.x, v.y, h01, l01);
            split2(v.z, v.w, h23, l23);
            uint32_t off = (uint32_t)(s*RST + k) * 2u;
            *(uint2*)(smc + SM_AHI + off) = make_uint2(h01, h23);
            *(uint2*)(smc + SM_ALO + off) = make_uint2(l01, l23);
        }
    }
    __syncthreads();   // sQf ready for fold

    // B1 fold: 2 adjacent k per thread, uint32 stores
    for (int t = tid; t < 8192; t += NTHR) {
        int k = (t & 31) * 2, n = t >> 5;
        int e = n*64 + k;
        float va = fmaf(sQf[k],   g_W1bT[e],   g_W1aT[e]);
        float vb = fmaf(sQf[k+1], g_W1bT[e+1], g_W1aT[e+1]);
        uint32_t hi, lo;
        split2(va, vb, hi, lo);
        uint32_t off = (uint32_t)(n*RST + k) * 2u;
        *(uint32_t*)(smc + SM_B1HI + off) = hi;
        *(uint32_t*)(smc + SM_B1LO + off) = lo;
    }
    __syncthreads();

    // ---- ldmatrix lane offsets ----
    const int lm = lane >> 3;            // matrix index 0..3
    const int lr = lane & 7;             // row within matrix
    const uint32_t aOff = (uint32_t)(((wid*16 + (lm&1)*8 + lr)*RST + (lm>>1)*8) * 2);
    const uint32_t bOff = (uint32_t)((((lm>>1)*8 + lr)*RST + (lm&1)*8) * 2);

    // ---- load A fragments once (16 rows/warp, reused for all heads) ----
    uint32_t ahi[4][4], alo[4][4];
    #pragma unroll
    for (int kc = 0; kc < 4; kc++) {
        ldm4(ahi[kc][0], ahi[kc][1], ahi[kc][2], ahi[kc][3], smb + SM_AHI + aOff + kc*32);
        ldm4(alo[kc][0], alo[kc][1], alo[kc][2], alo[kc][3], smb + SM_ALO + aOff + kc*32);
    }

    // ---- Phase C: per-head GEMM1 -> epilogue -> GEMM2 -> scores ----
    // Warps stagger their head order (wid&3 rotation) so at any instant
    // different warps occupy different pipes (ldm / tensor / epilogue-ALU).
    #pragma unroll 1
    for (int hh = 0; hh < NH; hh++) {
        const int h = (hh + (wid & 3)) & 3;
        const float al1 = sMiscf[4+h];
        const float al2 = sMiscf[8+h];

        float acc[8][4];
        #pragma unroll
        for (int nf = 0; nf < 8; nf++)
            #pragma unroll
            for (int r = 0; r < 4; r++) acc[nf][r] = 0.f;

        // B1hi loop: feeds BOTH (ahi x bhi) and (alo x bhi)
        {
            const uint32_t bbase = smb + SM_B1HI + (uint32_t)(h*64*RST*2) + bOff;
            #pragma unroll
            for (int kc = 0; kc < 4; kc++) {
                uint32_t bf[8][2];
                #pragma unroll
                for (int q = 0; q < 4; q++)
                    ldm4(bf[2*q][0], bf[2*q][1], bf[2*q+1][0], bf[2*q+1][1],
                         bbase + (uint32_t)(q*16*RST*2) + kc*32);
                #pragma unroll
                for (int nf = 0; nf < 8; nf++)
                    mma16816(acc[nf], ahi[kc], bf[nf]);
                #pragma unroll
                for (int nf = 0; nf < 8; nf++)
                    mma16816(acc[nf], alo[kc], bf[nf]);
            }
        }
        // B1lo loop: feeds (ahi x blo) only
        {
            const uint32_t bbase = smb + SM_B1LO + (uint32_t)(h*64*RST*2) + bOff;
            #pragma unroll
            for (int kc = 0; kc < 4; kc++) {
                uint32_t bf[8][2];
                #pragma unroll
                for (int q = 0; q < 4; q++)
                    ldm4(bf[2*q][0], bf[2*q][1], bf[2*q+1][0], bf[2*q+1][1],
                         bbase + (uint32_t)(q*16*RST*2) + kc*32);
                #pragma unroll
                for (int nf = 0; nf < 8; nf++)
                    mma16816(acc[nf], ahi[kc], bf[nf]);
            }
        }

        // epilogue 1: +c1, PReLU -> split into A2 fragments (C->A remap)
        uint32_t a2h[4][4], a2l[4][4];
        #pragma unroll
        for (int nf = 0; nf < 8; nf++) {
            float2 c1v = *(const float2*)(sC1f + h*64 + nf*8 + 2*gc);
            float v0 = acc[nf][0] + c1v.x;
            float v1 = acc[nf][1] + c1v.y;
            float v2 = acc[nf][2] + c1v.x;
            float v3 = acc[nf][3] + c1v.y;
            acc[nf][0] = v0 > 0.f ? v0 : al1*v0;
            acc[nf][1] = v1 > 0.f ? v1 : al1*v1;
            acc[nf][2] = v2 > 0.f ? v2 : al1*v2;
            acc[nf][3] = v3 > 0.f ? v3 : al1*v3;
        }
        #pragma unroll
        for (int kc = 0; kc < 4; kc++) {
            const float* cA = acc[2*kc];
            const float* cB = acc[2*kc+1];
            split2(cA[0], cA[1], a2h[kc][0], a2l[kc][0]);
            split2(cA[2], cA[3], a2h[kc][1], a2l[kc][1]);
            split2(cB[0], cB[1], a2h[kc][2], a2l[kc][2]);
            split2(cB[2], cB[3], a2h[kc][3], a2l[kc][3]);
        }

        // GEMM2: acc2[4n]
        float acc2[4][4];
        #pragma unroll
        for (int nf = 0; nf < 4; nf++)
            #pragma unroll
            for (int r = 0; r < 4; r++) acc2[nf][r] = 0.f;

        // B2hi loop: feeds (a2h x bhi) and (a2l x bhi)
        {
            const uint32_t bbase = smb + SM_B2HI + (uint32_t)(h*32*RST*2) + bOff;
            #pragma unroll
            for (int kc = 0; kc < 4; kc++) {
                uint32_t bf[4][2];
                #pragma unroll
                for (int q = 0; q < 2; q++)
                    ldm4(bf[2*q][0], bf[2*q][1], bf[2*q+1][0], bf[2*q+1][1],
                         bbase + (uint32_t)(q*16*RST*2) + kc*32);
                #pragma unroll
                for (int nf = 0; nf < 4; nf++)
                    mma16816(acc2[nf], a2h[kc], bf[nf]);
                #pragma unroll
                for (int nf = 0; nf < 4; nf++)
                    mma16816(acc2[nf], a2l[kc], bf[nf]);
            }
        }
        // B2lo loop: feeds (a2h x blo)
        {
            const uint32_t bbase = smb + SM_B2LO + (uint32_t)(h*32*RST*2) + bOff;
            #pragma unroll
            for (int kc = 0; kc < 4; kc++) {
                uint32_t bf[4][2];
                #pragma unroll
                for (int q = 0; q < 2; q++)
                    ldm4(bf[2*q][0], bf[2*q][1], bf[2*q+1][0], bf[2*q+1][1],
                         bbase + (uint32_t)(q*16*RST*2) + kc*32);
                #pragma unroll
                for (int nf = 0; nf < 4; nf++)
                    mma16816(acc2[nf], a2h[kc], bf[nf]);
            }
        }

        // epilogue 2: +b2, PReLU, dot W3, 4-lane reduce -> scores
        const float b3h = sMiscf[h];
        {
            float p0 = 0.f, p1 = 0.f;
            #pragma unroll
            for (int nf = 0; nf < 4; nf++) {
                int j0 = h*32 + nf*8 + 2*gc;
                float2 bb = *(const float2*)(sB2bf + j0);
                float2 ww = *(const float2*)(sW3f + j0);
                float v0 = acc2[nf][0] + bb.x;
                float v1 = acc2[nf][1] + bb.y;
                float v2 = acc2[nf][2] + bb.x;
                float v3 = acc2[nf][3] + bb.y;
                v0 = v0 > 0.f ? v0 : al2*v0;
                v1 = v1 > 0.f ? v1 : al2*v1;
                v2 = v2 > 0.f ? v2 : al2*v2;
                v3 = v3 > 0.f ? v3 : al2*v3;
                p0 = fmaf(v0, ww.x, fmaf(v1, ww.y, p0));
                p1 = fmaf(v2, ww.x, fmaf(v3, ww.y, p1));
            }
            p0 += __shfl_xor_sync(0xffffffffu, p0, 1);
            p0 += __shfl_xor_sync(0xffffffffu, p0, 2);
            p1 += __shfl_xor_sync(0xffffffffu, p1, 1);
            p1 += __shfl_xor_sync(0xffffffffu, p1, 2);
            if (gc == 0) {
                int gr = lane >> 2;
                int s = wid*16 + gr;
                if (s < NSP)   sScf[h*NSP + s]   = (sMaskf[s]   != 0.f) ? (p0 + b3h) : -FLT_MAX;
                if (s+8 < NSP) sScf[h*NSP + s+8] = (sMaskf[s+8] != 0.f) ? (p1 + b3h) : -FLT_MAX;
            }
        }
    }
    __syncthreads();

    // ---- Phase D (warps 0-3) overlapped with fp32-keys reload (warps 4-15) ----
    if (wid < NH) {
        float* row = sScf + wid*NSP;
        float m = -FLT_MAX;
        for (int t = lane; t < NS; t += 32) m = fmaxf(m, row[t]);
        #pragma unroll
        for (int o = 16; o > 0; o >>= 1) m = fmaxf(m, __shfl_xor_sync(0xffffffffu, m, o));
        float sum = 0.f;
        for (int t = lane; t < NS; t += 32) {
            float v = row[t];
            float e = (v > -1e38f) ? expf(v - m) : 0.f;
            row[t] = e;
            sum += e;
        }
        #pragma unroll
        for (int o = 16; o > 0; o >>= 1) sum += __shfl_xor_sync(0xffffffffu, sum, o);
        float inv = (sum > 0.f) ? (1.f / sum) : 0.f;
        for (int t = lane; t < NS; t += 32) row[t] *= inv;
    } else {
        int t2 = tid - 128;                        // 0..383
        for (int t = t2; t < 832; t += 384) {      // pad cols 200..212
            int d = t / 13, p = 200 + t % 13;
            sKf[d*KST + p] = 0.f;
        }
        const float4* kg = (const float4*)(keys + (size_t)b * (NS*ND));
        for (int t = t2; t < 3200; t += 384) {
            float4 v = kg[t];
            int e = t*4, s = e>>6, d = e&63;
            float* dst = sKf + d*KST + s;
            dst[0*KST]=v.x; dst[1*KST]=v.y; dst[2*KST]=v.z; dst[3*KST]=v.w;
        }
    }
    __syncthreads();

    // ---- Phase E: weighted sum, head mean, out projection ----
    if (tid < NH*ND) {
        int h = tid >> 6, d = tid & 63;
        const float* w    = sScf + h*NSP;
        const float* kcol = sKf + d*KST;
        float a0 = 0.f, a1_ = 0.f, a2_ = 0.f, a3_ = 0.f;
        #pragma unroll 4
        for (int t = 0; t < NS; t += 4) {
            a0  = fmaf(w[t  ], kcol[t  ], a0);
            a1_ = fmaf(w[t+1], kcol[t+1], a1_);
            a2_ = fmaf(w[t+2], kcol[t+2], a2_);
            a3_ = fmaf(w[t+3], kcol[t+3], a3_);
        }
        sOutH[tid] = (a0 + a1_) + (a2_ + a3_);
    }
    __syncthreads();
    if (tid < ND) {
        float c = 0.25f * (sOutH[tid] + sOutH[64+tid] + sOutH[128+tid] + sOutH[192+tid]);
        sMiscf[16 + tid] = c;
    }
    __syncthreads();
    if (tid < ND) {
        float e0 = bo[tid], e1 = 0.f;
        #pragma unroll 4
        for (int d2 = 0; d2 < ND; d2 += 2) {
            e0 = fmaf(sMiscf[16 + d2],     Wo[(d2  )*ND + tid], e0);
            e1 = fmaf(sMiscf[16 + d2 + 1], Wo[(d2+1)*ND + tid], e1);
        }
        out[b*ND + tid] = e0 + e1;
    }
}

extern "C" void kernel_launch(void* const* d_in, const int* in_sizes, int n_in,
                              void* d_out, int out_size) {
    const float* query = (const float*)d_in[0];
    const float* keys  = (const float*)d_in[1];
    const int*   kmask = (const int*)  d_in[2];
    const float* W1    = (const float*)d_in[3];
    const float* b1    = (const float*)d_in[4];
    const float* a1    = (const float*)d_in[5];
    const float* W2    = (const float*)d_in[6];
    const float* b2    = (const float*)d_in[7];
    const float* a2    = (const float*)d_in[8];
    const float* W3    = (const float*)d_in[9];
    const float* b3    = (const float*)d_in[10];
    const float* Wo    = (const float*)d_in[11];
    const float* bo    = (const float*)d_in[12];
    float* out = (float*)d_out;

    cudaFuncSetAttribute(attn_main, cudaFuncAttributeMaxDynamicSharedMemorySize, SMEM_BYTES);

    prep_w1<<<64, 256>>>(W1);
    prep_w2<<<36, 256>>>(W2);
    prep_c1<<<64, 256>>>(query, b1);
    attn_main<<<NB, NTHR, SMEM_BYTES>>>(
        query, keys, kmask, a1, b2, a2, W3, b3, Wo, bo, out);
}